// round 1
// baseline (speedup 1.0000x reference)
#include <cuda_runtime.h>
#include <math.h>
#include <stdint.h>
#include <stddef.h>

// Problem dims (fixed)
#define TT 2048
#define BB 2
#define CC 512
#define HH 8
#define HDD 64
#define FF 2048
#define NLAYER 4
#define MR (TT*BB)          // 4096 rows for all linear layers
#define BHH (BB*HH)         // 16 attention batches
#define WN ((size_t)BHH*TT*TT)   // 67,108,864 score elements
#define NPART 1024

// ---------------- scratch (device globals; no allocs allowed) ----------------
__device__ float g_x[MR*CC];            // running activation [T*B, C]
__device__ float g_tmp[MR*CC];          // attn/ffn output before residual+LN
__device__ float g_qkv[MR*3*CC];        // self-attn qkv
__device__ float g_q[MR*CC];            // cross q / merged-head scratch
__device__ float g_kv[MR*2*CC];         // cross kv
__device__ float g_qh[BHH*TT*HDD];
__device__ float g_kh[BHH*TT*HDD];
__device__ float g_vh[BHH*TT*HDD];
__device__ float g_ah[BHH*TT*HDD];
__device__ float g_w[WN];               // 256 MB score tensor
__device__ float g_h[MR*FF];            // FFN hidden
__device__ float g_pmin[NPART];
__device__ float g_pmax[NPART];
__device__ float g_mm[2];               // [min, max]

// ---------------- positional embedding + input add ----------------
__global__ void __launch_bounds__(256) pos_embed_kernel(
    const float* __restrict__ xin, const int* __restrict__ tokens)
{
    int idx = blockIdx.x * 256 + threadIdx.x;
    if (idx >= MR*CC) return;
    int c = idx & (CC-1);
    int r = idx >> 9;           // row = t*B + b
    int b = r & 1;
    int t = r >> 1;
    float pe = 0.f;
    if (tokens[b*TT + t] != 0) {
        int j = (c < 256) ? c : c - 256;
        // freq = exp(j * (-ln(10000)/255)), fp32 like the reference
        float freq = expf((float)j * (-9.210340371976184f / 255.0f));
        float ang = (float)(t + 1) * freq;
        pe = (c < 256) ? sinf(ang) : cosf(ang);
    }
    g_x[idx] = xin[idx] + pe;
}

// ---------------- generic TN GEMM: out[M,N] = A[M,K] @ W[N,K]^T + bias ----------------
template<bool RELU>
__global__ void __launch_bounds__(256) gemm_tn(
    const float* __restrict__ A, const float* __restrict__ W,
    const float* __restrict__ bias, float* __restrict__ out,
    int M, int N, int K)
{
    __shared__ float As[16][65];
    __shared__ float Ws[16][65];
    const int tid = threadIdx.x;
    const int tx = tid & 15, ty = tid >> 4;
    const int m0 = blockIdx.y << 6, n0 = blockIdx.x << 6;
    const int lrow = tid >> 2;
    const int lk = (tid & 3) << 2;
    float acc[4][4];
    #pragma unroll
    for (int i = 0; i < 4; i++)
        #pragma unroll
        for (int j = 0; j < 4; j++) acc[i][j] = 0.f;

    const float* Ap = A + (size_t)(m0 + lrow) * K + lk;
    const float* Wp = W + (size_t)(n0 + lrow) * K + lk;
    for (int k0 = 0; k0 < K; k0 += 16) {
        float4 av = *(const float4*)(Ap + k0);
        float4 wv = *(const float4*)(Wp + k0);
        As[lk+0][lrow] = av.x; As[lk+1][lrow] = av.y;
        As[lk+2][lrow] = av.z; As[lk+3][lrow] = av.w;
        Ws[lk+0][lrow] = wv.x; Ws[lk+1][lrow] = wv.y;
        Ws[lk+2][lrow] = wv.z; Ws[lk+3][lrow] = wv.w;
        __syncthreads();
        #pragma unroll
        for (int k = 0; k < 16; k++) {
            float ar[4], br[4];
            #pragma unroll
            for (int i = 0; i < 4; i++) ar[i] = As[k][(ty<<2)+i];
            #pragma unroll
            for (int j = 0; j < 4; j++) br[j] = Ws[k][(tx<<2)+j];
            #pragma unroll
            for (int i = 0; i < 4; i++)
                #pragma unroll
                for (int j = 0; j < 4; j++)
                    acc[i][j] = fmaf(ar[i], br[j], acc[i][j]);
        }
        __syncthreads();
    }
    #pragma unroll
    for (int i = 0; i < 4; i++) {
        int m = m0 + (ty<<2) + i;
        #pragma unroll
        for (int j = 0; j < 4; j++) {
            int n = n0 + (tx<<2) + j;
            float v = acc[i][j] + bias[n];
            if (RELU) v = fmaxf(v, 0.f);
            out[(size_t)m * N + n] = v;
        }
    }
}

// ---------------- split heads: row-major [T*B, ...] -> [B*H, T, hd], q scaled ----------------
__global__ void __launch_bounds__(256) split_heads(
    const float* __restrict__ qsrc, int qld,
    const float* __restrict__ ksrc, int kld,
    const float* __restrict__ vsrc, int vld)
{
    int idx = blockIdx.x * 256 + threadIdx.x;
    if (idx >= BHH*TT*HDD) return;
    int d  = idx & 63;
    int t  = (idx >> 6) & (TT-1);
    int bh = idx >> 17;            // HDD*TT = 2^17
    int b = bh >> 3, h = bh & 7;
    size_t r = (size_t)t * BB + b;
    int c = h * HDD + d;
    g_qh[idx] = qsrc[r * qld + c] * 0.125f;   // hd^-0.5 = 64^-0.5
    g_kh[idx] = ksrc[r * kld + c];
    g_vh[idx] = vsrc[r * vld + c];
}

// ---------------- batched scores: w[bh,t,s] = q.k  (mask applied, zero fast-path) ----------------
__global__ void __launch_bounds__(256) attn_scores(
    const float* __restrict__ qh, const float* __restrict__ kh,
    float* __restrict__ w, int causal)
{
    const int bh = blockIdx.z;
    const int t0 = blockIdx.y << 6, s0 = blockIdx.x << 6;
    const int tid = threadIdx.x, tx = tid & 15, ty = tid >> 4;
    float* wb = w + (size_t)bh * TT * TT;

    if (causal && s0 >= t0 + 64) {   // fully above diagonal -> zeros, skip compute
        #pragma unroll
        for (int i = 0; i < 4; i++)
            #pragma unroll
            for (int j = 0; j < 4; j++)
                wb[(size_t)(t0+(ty<<2)+i)*TT + s0+(tx<<2)+j] = 0.f;
        return;
    }

    __shared__ float Qs[64][65];
    __shared__ float Ks[64][65];
    const float* qb = qh + ((size_t)bh*TT + t0) * HDD;
    const float* kb = kh + ((size_t)bh*TT + s0) * HDD;
    #pragma unroll
    for (int rep = 0; rep < 4; rep++) {
        int lin = rep*256 + tid;
        int row = lin >> 4, d4 = (lin & 15) << 2;
        float4 q4 = *(const float4*)(qb + row*HDD + d4);
        float4 k4 = *(const float4*)(kb + row*HDD + d4);
        Qs[row][d4+0]=q4.x; Qs[row][d4+1]=q4.y; Qs[row][d4+2]=q4.z; Qs[row][d4+3]=q4.w;
        Ks[row][d4+0]=k4.x; Ks[row][d4+1]=k4.y; Ks[row][d4+2]=k4.z; Ks[row][d4+3]=k4.w;
    }
    __syncthreads();

    float acc[4][4];
    #pragma unroll
    for (int i = 0; i < 4; i++)
        #pragma unroll
        for (int j = 0; j < 4; j++) acc[i][j] = 0.f;
    #pragma unroll
    for (int k = 0; k < 64; k++) {
        float ar[4], br[4];
        #pragma unroll
        for (int i = 0; i < 4; i++) ar[i] = Qs[(ty<<2)+i][k];
        #pragma unroll
        for (int j = 0; j < 4; j++) br[j] = Ks[(tx<<2)+j][k];
        #pragma unroll
        for (int i = 0; i < 4; i++)
            #pragma unroll
            for (int j = 0; j < 4; j++)
                acc[i][j] = fmaf(ar[i], br[j], acc[i][j]);
    }
    #pragma unroll
    for (int i = 0; i < 4; i++) {
        int t = t0 + (ty<<2) + i;
        #pragma unroll
        for (int j = 0; j < 4; j++) {
            int s = s0 + (tx<<2) + j;
            float v = acc[i][j];
            if (causal && s > t) v = 0.f;
            wb[(size_t)t*TT + s] = v;
        }
    }
}

// ---------------- global min/max over w (two-stage, deterministic) ----------------
__global__ void __launch_bounds__(256) minmax_partial(const float* __restrict__ w)
{
    __shared__ float smin[256], smax[256];
    const int tid = threadIdx.x;
    float lo = 3.4e38f, hi = -3.4e38f;
    const float4* w4 = (const float4*)w;
    const size_t n4 = WN / 4;
    for (size_t i = (size_t)blockIdx.x*256 + tid; i < n4; i += (size_t)NPART*256) {
        float4 v = w4[i];
        lo = fminf(lo, fminf(fminf(v.x, v.y), fminf(v.z, v.w)));
        hi = fmaxf(hi, fmaxf(fmaxf(v.x, v.y), fmaxf(v.z, v.w)));
    }
    smin[tid] = lo; smax[tid] = hi;
    __syncthreads();
    for (int s = 128; s > 0; s >>= 1) {
        if (tid < s) {
            smin[tid] = fminf(smin[tid], smin[tid+s]);
            smax[tid] = fmaxf(smax[tid], smax[tid+s]);
        }
        __syncthreads();
    }
    if (tid == 0) { g_pmin[blockIdx.x] = smin[0]; g_pmax[blockIdx.x] = smax[0]; }
}

__global__ void __launch_bounds__(256) minmax_final()
{
    __shared__ float smin[256], smax[256];
    const int tid = threadIdx.x;
    float lo = 3.4e38f, hi = -3.4e38f;
    #pragma unroll
    for (int r = 0; r < NPART/256; r++) {
        lo = fminf(lo, g_pmin[r*256 + tid]);
        hi = fmaxf(hi, g_pmax[r*256 + tid]);
    }
    smin[tid] = lo; smax[tid] = hi;
    __syncthreads();
    for (int s = 128; s > 0; s >>= 1) {
        if (tid < s) {
            smin[tid] = fminf(smin[tid], smin[tid+s]);
            smax[tid] = fmaxf(smax[tid], smax[tid+s]);
        }
        __syncthreads();
    }
    if (tid == 0) { g_mm[0] = smin[0]; g_mm[1] = smax[0]; }
}

__global__ void __launch_bounds__(256) normalize_w(float* __restrict__ w)
{
    const float mn = g_mm[0];
    const float inv = 1.0f / (g_mm[1] - mn);
    float4* w4 = (float4*)w;
    const size_t n4 = WN / 4;
    for (size_t i = (size_t)blockIdx.x*256 + threadIdx.x; i < n4;
         i += (size_t)gridDim.x*256) {
        float4 v = w4[i];
        v.x = (v.x - mn) * inv; v.y = (v.y - mn) * inv;
        v.z = (v.z - mn) * inv; v.w = (v.w - mn) * inv;
        w4[i] = v;
    }
}

// ---------------- batched AV: ah[bh,t,d] = sum_s w[bh,t,s] * vh[bh,s,d] ----------------
__global__ void __launch_bounds__(256) attn_av(
    const float* __restrict__ w, const float* __restrict__ vh,
    float* __restrict__ ah)
{
    const int bh = blockIdx.z;
    const int t0 = blockIdx.y << 6;
    const int tid = threadIdx.x, tx = tid & 15, ty = tid >> 4;
    __shared__ float Wsh[64][33];
    __shared__ float Vs[32][65];
    const float* wb = w + (size_t)bh * TT * TT;
    const float* vb = vh + (size_t)bh * TT * HDD;

    float acc[4][4];
    #pragma unroll
    for (int i = 0; i < 4; i++)
        #pragma unroll
        for (int j = 0; j < 4; j++) acc[i][j] = 0.f;

    for (int s0 = 0; s0 < TT; s0 += 32) {
        #pragma unroll
        for (int rep = 0; rep < 2; rep++) {
            int lin = rep*256 + tid;          // 0..511
            int row = lin >> 3, s4 = (lin & 7) << 2;
            float4 w4 = *(const float4*)(wb + (size_t)(t0+row)*TT + s0 + s4);
            Wsh[row][s4+0]=w4.x; Wsh[row][s4+1]=w4.y; Wsh[row][s4+2]=w4.z; Wsh[row][s4+3]=w4.w;
            int vrow = lin >> 4, d4 = (lin & 15) << 2;
            float4 v4 = *(const float4*)(vb + (size_t)(s0+vrow)*HDD + d4);
            Vs[vrow][d4+0]=v4.x; Vs[vrow][d4+1]=v4.y; Vs[vrow][d4+2]=v4.z; Vs[vrow][d4+3]=v4.w;
        }
        __syncthreads();
        #pragma unroll
        for (int k = 0; k < 32; k++) {
            float ar[4], br[4];
            #pragma unroll
            for (int i = 0; i < 4; i++) ar[i] = Wsh[(ty<<2)+i][k];
            #pragma unroll
            for (int j = 0; j < 4; j++) br[j] = Vs[k][(tx<<2)+j];
            #pragma unroll
            for (int i = 0; i < 4; i++)
                #pragma unroll
                for (int j = 0; j < 4; j++)
                    acc[i][j] = fmaf(ar[i], br[j], acc[i][j]);
        }
        __syncthreads();
    }
    #pragma unroll
    for (int i = 0; i < 4; i++)
        #pragma unroll
        for (int j = 0; j < 4; j++)
            ah[((size_t)bh*TT + t0+(ty<<2)+i)*HDD + (tx<<2)+j] = acc[i][j];
}

// ---------------- merge heads: [B*H, T, hd] -> [T*B, C] ----------------
__global__ void __launch_bounds__(256) merge_heads(float* __restrict__ a)
{
    int idx = blockIdx.x * 256 + threadIdx.x;
    if (idx >= MR*CC) return;
    int c = idx & (CC-1);
    int r = idx >> 9;
    int b = r & 1;
    int t = r >> 1;
    int h = c >> 6, d = c & 63;
    a[idx] = g_ah[((size_t)(b*HH + h)*TT + t)*HDD + d];
}

// ---------------- residual add + LayerNorm (in-place on x) ----------------
__global__ void __launch_bounds__(128) add_ln(
    float* __restrict__ x, const float* __restrict__ dlt,
    const float* __restrict__ g, const float* __restrict__ b)
{
    const int r = blockIdx.x;
    const int tid = threadIdx.x;
    __shared__ float sred[128];
    float4 xv = *(float4*)(x + (size_t)r*CC + tid*4);
    float4 dv = *(const float4*)(dlt + (size_t)r*CC + tid*4);
    float y0 = xv.x+dv.x, y1 = xv.y+dv.y, y2 = xv.z+dv.z, y3 = xv.w+dv.w;

    sred[tid] = y0+y1+y2+y3;
    __syncthreads();
    for (int s = 64; s > 0; s >>= 1) {
        if (tid < s) sred[tid] += sred[tid+s];
        __syncthreads();
    }
    float mu = sred[0] * (1.0f/CC);
    __syncthreads();

    float d0 = y0-mu, d1 = y1-mu, d2 = y2-mu, d3 = y3-mu;
    sred[tid] = d0*d0 + d1*d1 + d2*d2 + d3*d3;
    __syncthreads();
    for (int s = 64; s > 0; s >>= 1) {
        if (tid < s) sred[tid] += sred[tid+s];
        __syncthreads();
    }
    float rstd = rsqrtf(sred[0] * (1.0f/CC) + 1e-20f);

    float4 gv = *(const float4*)(g + tid*4);
    float4 bv = *(const float4*)(b + tid*4);
    float4 ov;
    ov.x = d0*rstd*gv.x + bv.x;
    ov.y = d1*rstd*gv.y + bv.y;
    ov.z = d2*rstd*gv.z + bv.z;
    ov.w = d3*rstd*gv.w + bv.w;
    *(float4*)(x + (size_t)r*CC + tid*4) = ov;
}

__global__ void __launch_bounds__(256) copy_out(float* __restrict__ out)
{
    int idx = blockIdx.x * 256 + threadIdx.x;
    if (idx < MR*CC) out[idx] = g_x[idx];
}

// ---------------- host orchestration ----------------
static void run_attention(float* pw, float* pqh, float* pkh, float* pvh,
                          float* pah, float* pmerged, int causal)
{
    attn_scores<<<dim3(TT/64, TT/64, BHH), 256>>>(pqh, pkh, pw, causal);
    minmax_partial<<<NPART, 256>>>(pw);
    minmax_final<<<1, 256>>>();
    normalize_w<<<8192, 256>>>(pw);
    attn_av<<<dim3(1, TT/64, BHH), 256>>>(pw, pvh, pah);
    merge_heads<<<MR*CC/256, 256>>>(pmerged);
}

extern "C" void kernel_launch(void* const* d_in, const int* in_sizes, int n_in,
                              void* d_out, int out_size)
{
    const float* x       = (const float*)d_in[0];
    const float* enc     = (const float*)d_in[1];
    const int*   tokens  = (const int*)  d_in[2];
    const float* sWqkv   = (const float*)d_in[3];
    const float* sbqkv   = (const float*)d_in[4];
    const float* sWo     = (const float*)d_in[5];
    const float* sbo     = (const float*)d_in[6];
    const float* cWqkv   = (const float*)d_in[7];
    const float* cbqkv   = (const float*)d_in[8];
    const float* cWo     = (const float*)d_in[9];
    const float* cbo     = (const float*)d_in[10];
    const float* fc1w    = (const float*)d_in[11];
    const float* fc1b    = (const float*)d_in[12];
    const float* fc2w    = (const float*)d_in[13];
    const float* fc2b    = (const float*)d_in[14];
    const float* ln1g    = (const float*)d_in[15];
    const float* ln1b    = (const float*)d_in[16];
    const float* ln2g    = (const float*)d_in[17];
    const float* ln2b    = (const float*)d_in[18];
    const float* ln3g    = (const float*)d_in[19];
    const float* ln3b    = (const float*)d_in[20];

    float *px, *ptmp, *pqkv, *pq, *pkv, *pqh, *pkh, *pvh, *pah, *pw, *ph;
    cudaGetSymbolAddress((void**)&px,   g_x);
    cudaGetSymbolAddress((void**)&ptmp, g_tmp);
    cudaGetSymbolAddress((void**)&pqkv, g_qkv);
    cudaGetSymbolAddress((void**)&pq,   g_q);
    cudaGetSymbolAddress((void**)&pkv,  g_kv);
    cudaGetSymbolAddress((void**)&pqh,  g_qh);
    cudaGetSymbolAddress((void**)&pkh,  g_kh);
    cudaGetSymbolAddress((void**)&pvh,  g_vh);
    cudaGetSymbolAddress((void**)&pah,  g_ah);
    cudaGetSymbolAddress((void**)&pw,   g_w);
    cudaGetSymbolAddress((void**)&ph,   g_h);

    // x = x + positional embedding
    pos_embed_kernel<<<MR*CC/256, 256>>>(x, tokens);

    for (int l = 0; l < NLAYER; l++) {
        const float* sWqkv_l = sWqkv + (size_t)l*3*CC*CC;
        const float* sbqkv_l = sbqkv + (size_t)l*3*CC;
        const float* sWo_l   = sWo   + (size_t)l*CC*CC;
        const float* sbo_l   = sbo   + (size_t)l*CC;
        const float* cWqkv_l = cWqkv + (size_t)l*3*CC*CC;
        const float* cbqkv_l = cbqkv + (size_t)l*3*CC;
        const float* cWo_l   = cWo   + (size_t)l*CC*CC;
        const float* cbo_l   = cbo   + (size_t)l*CC;
        const float* fc1w_l  = fc1w  + (size_t)l*FF*CC;
        const float* fc1b_l  = fc1b  + (size_t)l*FF;
        const float* fc2w_l  = fc2w  + (size_t)l*CC*FF;
        const float* fc2b_l  = fc2b  + (size_t)l*CC;

        // ---- self-attention ----
        gemm_tn<false><<<dim3(3*CC/64, MR/64), 256>>>(px, sWqkv_l, sbqkv_l, pqkv, MR, 3*CC, CC);
        split_heads<<<BHH*TT*HDD/256, 256>>>(pqkv, 3*CC, pqkv + CC, 3*CC, pqkv + 2*CC, 3*CC);
        run_attention(pw, pqh, pkh, pvh, pah, pq, /*causal=*/1);
        gemm_tn<false><<<dim3(CC/64, MR/64), 256>>>(pq, sWo_l, sbo_l, ptmp, MR, CC, CC);
        add_ln<<<MR, 128>>>(px, ptmp, ln1g + l*CC, ln1b + l*CC);

        // ---- cross-attention ----
        gemm_tn<false><<<dim3(CC/64, MR/64), 256>>>(px, cWqkv_l, cbqkv_l, pq, MR, CC, CC);
        gemm_tn<false><<<dim3(2*CC/64, MR/64), 256>>>(enc, cWqkv_l + (size_t)CC*CC,
                                                      cbqkv_l + CC, pkv, MR, 2*CC, CC);
        split_heads<<<BHH*TT*HDD/256, 256>>>(pq, CC, pkv, 2*CC, pkv + CC, 2*CC);
        run_attention(pw, pqh, pkh, pvh, pah, pq, /*causal=*/0);
        gemm_tn<false><<<dim3(CC/64, MR/64), 256>>>(pq, cWo_l, cbo_l, ptmp, MR, CC, CC);
        add_ln<<<MR, 128>>>(px, ptmp, ln2g + l*CC, ln2b + l*CC);

        // ---- FFN ----
        gemm_tn<true ><<<dim3(FF/64, MR/64), 256>>>(px, fc1w_l, fc1b_l, ph, MR, FF, CC);
        gemm_tn<false><<<dim3(CC/64, MR/64), 256>>>(ph, fc2w_l, fc2b_l, ptmp, MR, CC, FF);
        add_ln<<<MR, 128>>>(px, ptmp, ln3g + l*CC, ln3b + l*CC);
    }

    copy_out<<<MR*CC/256, 256>>>((float*)d_out);
}

// round 2
// speedup vs baseline: 5.0928x; 5.0928x over previous
#include <cuda_runtime.h>
#include <cuda_bf16.h>
#include <math.h>
#include <stdint.h>
#include <stddef.h>

// Problem dims (fixed)
#define TT 2048
#define BB 2
#define CC 512
#define HH 8
#define HDD 64
#define FF 2048
#define NLAYER 4
#define MR (TT*BB)          // 4096 rows for all linear layers
#define BHH (BB*HH)         // 16 attention batches
#define WN ((size_t)BHH*TT*TT)

#define BM 128
#define BK 32

// ---------------- scratch (device globals; no allocs allowed) ----------------
__device__ float g_x[MR*CC];
__device__ float g_tmp[MR*CC];
__device__ float g_qkv[MR*3*CC];
__device__ float g_q[MR*CC];
__device__ float g_kv[MR*2*CC];
__device__ float g_qh[BHH*TT*HDD];
__device__ float g_kh[BHH*TT*HDD];
__device__ float g_vt[BHH*HDD*TT];      // V transposed: [bh][d][t]
__device__ float g_ah[BHH*TT*HDD];
__device__ float g_w[WN];               // 256 MB score tensor (raw, pre-norm)
__device__ float g_h[MR*FF];
__device__ unsigned g_enc[2];           // ordered-encoded min/max
__device__ float g_mm[2];               // [min, 1/(max-min)]

// ---------------- helpers ----------------
__device__ __forceinline__ unsigned fenc(float x) {
    unsigned u = __float_as_uint(x);
    return (u & 0x80000000u) ? ~u : (u | 0x80000000u);
}
__device__ __forceinline__ float fdec(unsigned e) {
    unsigned u = (e & 0x80000000u) ? (e & 0x7FFFFFFFu) : ~e;
    return __uint_as_float(u);
}

// split x into hi+lo bf16 pair (packed 2 values per 32-bit word, k-adjacent)
__device__ __forceinline__ void split2(float x0, float x1, unsigned &h, unsigned &l) {
    __nv_bfloat162 hb = __floats2bfloat162_rn(x0, x1);
    float r0 = x0 - __bfloat162float(hb.x);
    float r1 = x1 - __bfloat162float(hb.y);
    __nv_bfloat162 lb = __floats2bfloat162_rn(r0, r1);
    h = *reinterpret_cast<unsigned*>(&hb);
    l = *reinterpret_cast<unsigned*>(&lb);
}

__device__ __forceinline__ void mma_bf16(float (&d)[4], const unsigned (&a)[4], const unsigned (&b)[2]) {
    asm volatile("mma.sync.aligned.m16n8k16.row.col.f32.bf16.bf16.f32 "
        "{%0,%1,%2,%3},{%4,%5,%6,%7},{%8,%9},{%0,%1,%2,%3};\n"
        : "+f"(d[0]), "+f"(d[1]), "+f"(d[2]), "+f"(d[3])
        : "r"(a[0]), "r"(a[1]), "r"(a[2]), "r"(a[3]), "r"(b[0]), "r"(b[1]));
}

// ---------------- positional embedding + input add ----------------
__global__ void __launch_bounds__(256) pos_embed_kernel(
    const float* __restrict__ xin, const int* __restrict__ tokens)
{
    int idx = blockIdx.x * 256 + threadIdx.x;
    if (idx >= MR*CC) return;
    int c = idx & (CC-1);
    int r = idx >> 9;
    int b = r & 1;
    int t = r >> 1;
    float pe = 0.f;
    if (tokens[b*TT + t] != 0) {
        int j = (c < 256) ? c : c - 256;
        float freq = expf((float)j * (-9.210340371976184f / 255.0f));
        float ang = (float)(t + 1) * freq;
        pe = (c < 256) ? sinf(ang) : cosf(ang);
    }
    g_x[idx] = xin[idx] + pe;
}

// ================= split-bf16 TN GEMM: out[M,N] = A[M,K] @ W[N,K]^T + bias =================
template<bool RELU>
__global__ void __launch_bounds__(256, 1) gemm_bf16s(
    const float* __restrict__ A, const float* __restrict__ W,
    const float* __restrict__ bias, float* __restrict__ out,
    int N, int K)
{
    __shared__ unsigned Ah[BM*20], Al[BM*20], Bh[BM*20], Bl[BM*20];
    const int tid = threadIdx.x;
    const int m0 = blockIdx.y * BM, n0 = blockIdx.x * BM;
    const int prow = tid >> 3, pk = (tid & 7) << 2;
    const float* Ap = A + (size_t)(m0 + prow) * K + pk;
    const float* Wp = W + (size_t)(n0 + prow) * K + pk;

    float4 ra[4], rb[4];
    #pragma unroll
    for (int r = 0; r < 4; r++) {
        ra[r] = *(const float4*)(Ap + (size_t)r*32*K);
        rb[r] = *(const float4*)(Wp + (size_t)r*32*K);
    }

    const int wid = tid >> 5, lane = tid & 31;
    const int wy = wid >> 2, wx = wid & 3;
    const int lq = lane >> 2, lr = lane & 3;
    const int wm = wy * 64, wn = wx * 32;

    float acc[4][4][4];
    #pragma unroll
    for (int i = 0; i < 4; i++)
        #pragma unroll
        for (int j = 0; j < 4; j++)
            #pragma unroll
            for (int q = 0; q < 4; q++) acc[i][j][q] = 0.f;

    const int KT = K / BK;
    for (int kt = 0; kt < KT; kt++) {
        #pragma unroll
        for (int r = 0; r < 4; r++) {
            int ad = (prow + 32*r)*20 + (pk >> 1);
            unsigned h0,l0,h1,l1;
            split2(ra[r].x, ra[r].y, h0, l0); split2(ra[r].z, ra[r].w, h1, l1);
            *(uint2*)&Ah[ad] = make_uint2(h0, h1);
            *(uint2*)&Al[ad] = make_uint2(l0, l1);
            split2(rb[r].x, rb[r].y, h0, l0); split2(rb[r].z, rb[r].w, h1, l1);
            *(uint2*)&Bh[ad] = make_uint2(h0, h1);
            *(uint2*)&Bl[ad] = make_uint2(l0, l1);
        }
        __syncthreads();
        if (kt + 1 < KT) {
            #pragma unroll
            for (int r = 0; r < 4; r++) {
                ra[r] = *(const float4*)(Ap + (kt+1)*BK + (size_t)r*32*K);
                rb[r] = *(const float4*)(Wp + (kt+1)*BK + (size_t)r*32*K);
            }
        }
        #pragma unroll
        for (int ks = 0; ks < 2; ks++) {
            const int kw = ks * 8;
            unsigned ah[4][4], al_[4][4];
            #pragma unroll
            for (int mt = 0; mt < 4; mt++) {
                int ba = (wm + mt*16 + lq)*20 + kw + lr;
                ah[mt][0]=Ah[ba];     ah[mt][1]=Ah[ba+160];
                ah[mt][2]=Ah[ba+4];   ah[mt][3]=Ah[ba+164];
                al_[mt][0]=Al[ba];    al_[mt][1]=Al[ba+160];
                al_[mt][2]=Al[ba+4];  al_[mt][3]=Al[ba+164];
            }
            unsigned bh_[4][2], bl_[4][2];
            #pragma unroll
            for (int nt = 0; nt < 4; nt++) {
                int bb = (wn + nt*8 + lq)*20 + kw + lr;
                bh_[nt][0]=Bh[bb]; bh_[nt][1]=Bh[bb+4];
                bl_[nt][0]=Bl[bb]; bl_[nt][1]=Bl[bb+4];
            }
            #pragma unroll
            for (int mt = 0; mt < 4; mt++)
                #pragma unroll
                for (int nt = 0; nt < 4; nt++) {
                    mma_bf16(acc[mt][nt], ah[mt],  bh_[nt]);
                    mma_bf16(acc[mt][nt], ah[mt],  bl_[nt]);
                    mma_bf16(acc[mt][nt], al_[mt], bh_[nt]);
                }
        }
        __syncthreads();
    }

    #pragma unroll
    for (int mt = 0; mt < 4; mt++) {
        int m = m0 + wm + mt*16 + lq;
        #pragma unroll
        for (int nt = 0; nt < 4; nt++) {
            int n = n0 + wn + nt*8 + 2*lr;
            float2 bv = *(const float2*)(bias + n);
            float v0 = acc[mt][nt][0] + bv.x;
            float v1 = acc[mt][nt][1] + bv.y;
            float v2 = acc[mt][nt][2] + bv.x;
            float v3 = acc[mt][nt][3] + bv.y;
            if (RELU) { v0=fmaxf(v0,0.f); v1=fmaxf(v1,0.f); v2=fmaxf(v2,0.f); v3=fmaxf(v3,0.f); }
            *(float2*)(out + (size_t)m*N + n)     = make_float2(v0, v1);
            *(float2*)(out + (size_t)(m+8)*N + n) = make_float2(v2, v3);
        }
    }
}

// ================= scores: w[bh,t,s] = q.k (mask + fused global min/max) =================
__global__ void __launch_bounds__(256, 1) attn_scores_mma(
    const float* __restrict__ qh, const float* __restrict__ kh, int causal)
{
    const int bh = blockIdx.z;
    const int s0 = blockIdx.x * BM, t0 = blockIdx.y * BM;
    const int tid = threadIdx.x;
    float* wb = g_w + (size_t)bh * TT * TT;

    if (causal && s0 >= t0 + BM) {
        float4 z = make_float4(0.f, 0.f, 0.f, 0.f);
        #pragma unroll
        for (int i = 0; i < 16; i++) {
            int f4 = tid + 256*i;
            int row = f4 >> 5, c4 = (f4 & 31) << 2;
            *(float4*)(wb + (size_t)(t0+row)*TT + s0 + c4) = z;
        }
        if (tid == 0) {
            atomicMin(&g_enc[0], 0x80000000u);
            atomicMax(&g_enc[1], 0x80000000u);
        }
        return;
    }

    __shared__ unsigned Ah[BM*20], Al[BM*20], Bh[BM*20], Bl[BM*20];
    __shared__ float rlo[8], rhi[8];
    const int prow = tid >> 3, pk = (tid & 7) << 2;
    const float* Ap = qh + ((size_t)bh*TT + t0 + prow) * HDD + pk;
    const float* Bp = kh + ((size_t)bh*TT + s0 + prow) * HDD + pk;

    float4 ra[4], rb[4];
    #pragma unroll
    for (int r = 0; r < 4; r++) {
        ra[r] = *(const float4*)(Ap + (size_t)r*32*HDD);
        rb[r] = *(const float4*)(Bp + (size_t)r*32*HDD);
    }

    const int wid = tid >> 5, lane = tid & 31;
    const int wy = wid >> 2, wx = wid & 3;
    const int lq = lane >> 2, lr = lane & 3;
    const int wm = wy * 64, wn = wx * 32;

    float acc[4][4][4];
    #pragma unroll
    for (int i = 0; i < 4; i++)
        #pragma unroll
        for (int j = 0; j < 4; j++)
            #pragma unroll
            for (int q = 0; q < 4; q++) acc[i][j][q] = 0.f;

    #pragma unroll
    for (int kt = 0; kt < 2; kt++) {     // K = 64
        #pragma unroll
        for (int r = 0; r < 4; r++) {
            int ad = (prow + 32*r)*20 + (pk >> 1);
            unsigned h0,l0,h1,l1;
            split2(ra[r].x, ra[r].y, h0, l0); split2(ra[r].z, ra[r].w, h1, l1);
            *(uint2*)&Ah[ad] = make_uint2(h0, h1);
            *(uint2*)&Al[ad] = make_uint2(l0, l1);
            split2(rb[r].x, rb[r].y, h0, l0); split2(rb[r].z, rb[r].w, h1, l1);
            *(uint2*)&Bh[ad] = make_uint2(h0, h1);
            *(uint2*)&Bl[ad] = make_uint2(l0, l1);
        }
        __syncthreads();
        if (kt == 0) {
            #pragma unroll
            for (int r = 0; r < 4; r++) {
                ra[r] = *(const float4*)(Ap + BK + (size_t)r*32*HDD);
                rb[r] = *(const float4*)(Bp + BK + (size_t)r*32*HDD);
            }
        }
        #pragma unroll
        for (int ks = 0; ks < 2; ks++) {
            const int kw = ks * 8;
            unsigned ah[4][4], al_[4][4];
            #pragma unroll
            for (int mt = 0; mt < 4; mt++) {
                int ba = (wm + mt*16 + lq)*20 + kw + lr;
                ah[mt][0]=Ah[ba];     ah[mt][1]=Ah[ba+160];
                ah[mt][2]=Ah[ba+4];   ah[mt][3]=Ah[ba+164];
                al_[mt][0]=Al[ba];    al_[mt][1]=Al[ba+160];
                al_[mt][2]=Al[ba+4];  al_[mt][3]=Al[ba+164];
            }
            unsigned bh_[4][2], bl_[4][2];
            #pragma unroll
            for (int nt = 0; nt < 4; nt++) {
                int bb = (wn + nt*8 + lq)*20 + kw + lr;
                bh_[nt][0]=Bh[bb]; bh_[nt][1]=Bh[bb+4];
                bl_[nt][0]=Bl[bb]; bl_[nt][1]=Bl[bb+4];
            }
            #pragma unroll
            for (int mt = 0; mt < 4; mt++)
                #pragma unroll
                for (int nt = 0; nt < 4; nt++) {
                    mma_bf16(acc[mt][nt], ah[mt],  bh_[nt]);
                    mma_bf16(acc[mt][nt], ah[mt],  bl_[nt]);
                    mma_bf16(acc[mt][nt], al_[mt], bh_[nt]);
                }
        }
        __syncthreads();
    }

    float blo = 3.4e38f, bhi = -3.4e38f;
    #pragma unroll
    for (int mt = 0; mt < 4; mt++) {
        int m = t0 + wm + mt*16 + lq;
        #pragma unroll
        for (int nt = 0; nt < 4; nt++) {
            int n = s0 + wn + nt*8 + 2*lr;
            float v0 = acc[mt][nt][0], v1 = acc[mt][nt][1];
            float v2 = acc[mt][nt][2], v3 = acc[mt][nt][3];
            if (causal) {
                if (n     > m)   v0 = 0.f;
                if (n + 1 > m)   v1 = 0.f;
                if (n     > m+8) v2 = 0.f;
                if (n + 1 > m+8) v3 = 0.f;
            }
            blo = fminf(blo, fminf(fminf(v0, v1), fminf(v2, v3)));
            bhi = fmaxf(bhi, fmaxf(fmaxf(v0, v1), fmaxf(v2, v3)));
            *(float2*)(wb + (size_t)m*TT + n)     = make_float2(v0, v1);
            *(float2*)(wb + (size_t)(m+8)*TT + n) = make_float2(v2, v3);
        }
    }
    #pragma unroll
    for (int o = 16; o > 0; o >>= 1) {
        blo = fminf(blo, __shfl_xor_sync(0xFFFFFFFFu, blo, o));
        bhi = fmaxf(bhi, __shfl_xor_sync(0xFFFFFFFFu, bhi, o));
    }
    if (lane == 0) { rlo[wid] = blo; rhi[wid] = bhi; }
    __syncthreads();
    if (tid == 0) {
        float lo = rlo[0], hi = rhi[0];
        #pragma unroll
        for (int w = 1; w < 8; w++) { lo = fminf(lo, rlo[w]); hi = fmaxf(hi, rhi[w]); }
        atomicMin(&g_enc[0], fenc(lo));
        atomicMax(&g_enc[1], fenc(hi));
    }
}

// ================= AV: ah[bh,t,d] = sum_s norm(w[bh,t,s]) * v[bh,s,d] =================
// A = w (normalize fused), B = vT [bh][d][t]; BN=64
__global__ void __launch_bounds__(256, 1) attn_av_mma()
{
    __shared__ unsigned Ah[BM*20], Al[BM*20], Bh[64*20], Bl[64*20];
    const int bh = blockIdx.z;
    const int t0 = blockIdx.y * BM;
    const int tid = threadIdx.x;
    const float mn = g_mm[0], inv = g_mm[1];

    const int prow = tid >> 3, pk = (tid & 7) << 2;
    const float* Ap = g_w + ((size_t)bh*TT + t0 + prow) * TT + pk;
    const float* Bp = g_vt + ((size_t)bh*HDD + prow) * TT + pk;   // rows d (64)

    float4 ra[4], rb[2];
    #pragma unroll
    for (int r = 0; r < 4; r++) ra[r] = *(const float4*)(Ap + (size_t)r*32*TT);
    #pragma unroll
    for (int r = 0; r < 2; r++) rb[r] = *(const float4*)(Bp + (size_t)r*32*TT);

    const int wid = tid >> 5, lane = tid & 31;
    const int wy = wid >> 1, wx = wid & 1;       // 4 x 2 warps
    const int lq = lane >> 2, lr = lane & 3;
    const int wm = wy * 32, wn = wx * 32;

    float acc[2][4][4];
    #pragma unroll
    for (int i = 0; i < 2; i++)
        #pragma unroll
        for (int j = 0; j < 4; j++)
            #pragma unroll
            for (int q = 0; q < 4; q++) acc[i][j][q] = 0.f;

    const int KT = TT / BK;   // 64
    for (int kt = 0; kt < KT; kt++) {
        #pragma unroll
        for (int r = 0; r < 4; r++) {
            int ad = (prow + 32*r)*20 + (pk >> 1);
            unsigned h0,l0,h1,l1;
            split2((ra[r].x - mn)*inv, (ra[r].y - mn)*inv, h0, l0);
            split2((ra[r].z - mn)*inv, (ra[r].w - mn)*inv, h1, l1);
            *(uint2*)&Ah[ad] = make_uint2(h0, h1);
            *(uint2*)&Al[ad] = make_uint2(l0, l1);
        }
        #pragma unroll
        for (int r = 0; r < 2; r++) {
            int ad = (prow + 32*r)*20 + (pk >> 1);
            unsigned h0,l0,h1,l1;
            split2(rb[r].x, rb[r].y, h0, l0); split2(rb[r].z, rb[r].w, h1, l1);
            *(uint2*)&Bh[ad] = make_uint2(h0, h1);
            *(uint2*)&Bl[ad] = make_uint2(l0, l1);
        }
        __syncthreads();
        if (kt + 1 < KT) {
            #pragma unroll
            for (int r = 0; r < 4; r++) ra[r] = *(const float4*)(Ap + (kt+1)*BK + (size_t)r*32*TT);
            #pragma unroll
            for (int r = 0; r < 2; r++) rb[r] = *(const float4*)(Bp + (kt+1)*BK + (size_t)r*32*TT);
        }
        #pragma unroll
        for (int ks = 0; ks < 2; ks++) {
            const int kw = ks * 8;
            unsigned ah[2][4], al_[2][4];
            #pragma unroll
            for (int mt = 0; mt < 2; mt++) {
                int ba = (wm + mt*16 + lq)*20 + kw + lr;
                ah[mt][0]=Ah[ba];     ah[mt][1]=Ah[ba+160];
                ah[mt][2]=Ah[ba+4];   ah[mt][3]=Ah[ba+164];
                al_[mt][0]=Al[ba];    al_[mt][1]=Al[ba+160];
                al_[mt][2]=Al[ba+4];  al_[mt][3]=Al[ba+164];
            }
            unsigned bh_[4][2], bl_[4][2];
            #pragma unroll
            for (int nt = 0; nt < 4; nt++) {
                int bb = (wn + nt*8 + lq)*20 + kw + lr;
                bh_[nt][0]=Bh[bb]; bh_[nt][1]=Bh[bb+4];
                bl_[nt][0]=Bl[bb]; bl_[nt][1]=Bl[bb+4];
            }
            #pragma unroll
            for (int mt = 0; mt < 2; mt++)
                #pragma unroll
                for (int nt = 0; nt < 4; nt++) {
                    mma_bf16(acc[mt][nt], ah[mt],  bh_[nt]);
                    mma_bf16(acc[mt][nt], ah[mt],  bl_[nt]);
                    mma_bf16(acc[mt][nt], al_[mt], bh_[nt]);
                }
        }
        __syncthreads();
    }

    #pragma unroll
    for (int mt = 0; mt < 2; mt++) {
        int m = t0 + wm + mt*16 + lq;
        #pragma unroll
        for (int nt = 0; nt < 4; nt++) {
            int n = wn + nt*8 + 2*lr;
            *(float2*)(g_ah + ((size_t)bh*TT + m)*HDD + n)
                = make_float2(acc[mt][nt][0], acc[mt][nt][1]);
            *(float2*)(g_ah + ((size_t)bh*TT + m + 8)*HDD + n)
                = make_float2(acc[mt][nt][2], acc[mt][nt][3]);
        }
    }
}

// ---------------- min/max bookkeeping ----------------
__global__ void mm_reset() { g_enc[0] = 0xFFFFFFFFu; g_enc[1] = 0u; }
__global__ void mm_final() {
    float mn = fdec(g_enc[0]), mx = fdec(g_enc[1]);
    g_mm[0] = mn; g_mm[1] = 1.0f / (mx - mn);
}

// ---------------- split heads (q,k): [T*B, ...] -> [B*H, T, hd], q scaled ----------------
__global__ void __launch_bounds__(256) split_heads_qk(
    const float* __restrict__ qsrc, int qld,
    const float* __restrict__ ksrc, int kld)
{
    int idx = blockIdx.x * 256 + threadIdx.x;
    if (idx >= BHH*TT*HDD) return;
    int d  = idx & 63;
    int t  = (idx >> 6) & (TT-1);
    int bh = idx >> 17;
    int b = bh >> 3, h = bh & 7;
    size_t r = (size_t)t * BB + b;
    int c = h * HDD + d;
    g_qh[idx] = qsrc[r * qld + c] * 0.125f;
    g_kh[idx] = ksrc[r * kld + c];
}

// ---------------- transpose V into [bh][d][t] ----------------
__global__ void __launch_bounds__(256) transpose_v(
    const float* __restrict__ vsrc, int ldv)
{
    __shared__ float tile[32][33];
    const int bh = blockIdx.z;
    const int b = bh >> 3, h = bh & 7;
    const int t0 = blockIdx.x * 32, d0 = blockIdx.y * 32;
    const int tx = threadIdx.x & 31, ty = threadIdx.x >> 5;
    #pragma unroll
    for (int j = ty; j < 32; j += 8)
        tile[j][tx] = vsrc[(size_t)((t0 + j)*BB + b) * ldv + h*HDD + d0 + tx];
    __syncthreads();
    #pragma unroll
    for (int j = ty; j < 32; j += 8)
        g_vt[((size_t)bh*HDD + d0 + j) * TT + t0 + tx] = tile[tx][j];
}

// ---------------- merge heads: [B*H, T, hd] -> [T*B, C] ----------------
__global__ void __launch_bounds__(256) merge_heads(float* __restrict__ a)
{
    int idx = blockIdx.x * 256 + threadIdx.x;
    if (idx >= MR*CC) return;
    int c = idx & (CC-1);
    int r = idx >> 9;
    int b = r & 1;
    int t = r >> 1;
    int h = c >> 6, d = c & 63;
    a[idx] = g_ah[((size_t)(b*HH + h)*TT + t)*HDD + d];
}

// ---------------- residual add + LayerNorm (in-place on x) ----------------
__global__ void __launch_bounds__(128) add_ln(
    float* __restrict__ x, const float* __restrict__ dlt,
    const float* __restrict__ g, const float* __restrict__ b)
{
    const int r = blockIdx.x;
    const int tid = threadIdx.x;
    __shared__ float sred[128];
    float4 xv = *(float4*)(x + (size_t)r*CC + tid*4);
    float4 dv = *(const float4*)(dlt + (size_t)r*CC + tid*4);
    float y0 = xv.x+dv.x, y1 = xv.y+dv.y, y2 = xv.z+dv.z, y3 = xv.w+dv.w;

    sred[tid] = y0+y1+y2+y3;
    __syncthreads();
    for (int s = 64; s > 0; s >>= 1) {
        if (tid < s) sred[tid] += sred[tid+s];
        __syncthreads();
    }
    float mu = sred[0] * (1.0f/CC);
    __syncthreads();

    float d0 = y0-mu, d1 = y1-mu, d2 = y2-mu, d3 = y3-mu;
    sred[tid] = d0*d0 + d1*d1 + d2*d2 + d3*d3;
    __syncthreads();
    for (int s = 64; s > 0; s >>= 1) {
        if (tid < s) sred[tid] += sred[tid+s];
        __syncthreads();
    }
    float rstd = rsqrtf(sred[0] * (1.0f/CC) + 1e-20f);

    float4 gv = *(const float4*)(g + tid*4);
    float4 bv = *(const float4*)(b + tid*4);
    float4 ov;
    ov.x = d0*rstd*gv.x + bv.x;
    ov.y = d1*rstd*gv.y + bv.y;
    ov.z = d2*rstd*gv.z + bv.z;
    ov.w = d3*rstd*gv.w + bv.w;
    *(float4*)(x + (size_t)r*CC + tid*4) = ov;
}

__global__ void __launch_bounds__(256) copy_out(float* __restrict__ out)
{
    int idx = blockIdx.x * 256 + threadIdx.x;
    if (idx < MR*CC) out[idx] = g_x[idx];
}

// ---------------- host orchestration ----------------
static void run_attention(float* pqh, float* pkh, int causal)
{
    mm_reset<<<1, 1>>>();
    attn_scores_mma<<<dim3(TT/BM, TT/BM, BHH), 256>>>(pqh, pkh, causal);
    mm_final<<<1, 1>>>();
    attn_av_mma<<<dim3(1, TT/BM, BHH), 256>>>();
}

extern "C" void kernel_launch(void* const* d_in, const int* in_sizes, int n_in,
                              void* d_out, int out_size)
{
    const float* x       = (const float*)d_in[0];
    const float* enc     = (const float*)d_in[1];
    const int*   tokens  = (const int*)  d_in[2];
    const float* sWqkv   = (const float*)d_in[3];
    const float* sbqkv   = (const float*)d_in[4];
    const float* sWo     = (const float*)d_in[5];
    const float* sbo     = (const float*)d_in[6];
    const float* cWqkv   = (const float*)d_in[7];
    const float* cbqkv   = (const float*)d_in[8];
    const float* cWo     = (const float*)d_in[9];
    const float* cbo     = (const float*)d_in[10];
    const float* fc1w    = (const float*)d_in[11];
    const float* fc1b    = (const float*)d_in[12];
    const float* fc2w    = (const float*)d_in[13];
    const float* fc2b    = (const float*)d_in[14];
    const float* ln1g    = (const float*)d_in[15];
    const float* ln1b    = (const float*)d_in[16];
    const float* ln2g    = (const float*)d_in[17];
    const float* ln2b    = (const float*)d_in[18];
    const float* ln3g    = (const float*)d_in[19];
    const float* ln3b    = (const float*)d_in[20];

    float *px, *ptmp, *pqkv, *pq, *pkv, *pqh, *pkh, *ph;
    cudaGetSymbolAddress((void**)&px,   g_x);
    cudaGetSymbolAddress((void**)&ptmp, g_tmp);
    cudaGetSymbolAddress((void**)&pqkv, g_qkv);
    cudaGetSymbolAddress((void**)&pq,   g_q);
    cudaGetSymbolAddress((void**)&pkv,  g_kv);
    cudaGetSymbolAddress((void**)&pqh,  g_qh);
    cudaGetSymbolAddress((void**)&pkh,  g_kh);
    cudaGetSymbolAddress((void**)&ph,   g_h);

    pos_embed_kernel<<<MR*CC/256, 256>>>(x, tokens);

    for (int l = 0; l < NLAYER; l++) {
        const float* sWqkv_l = sWqkv + (size_t)l*3*CC*CC;
        const float* sbqkv_l = sbqkv + (size_t)l*3*CC;
        const float* sWo_l   = sWo   + (size_t)l*CC*CC;
        const float* sbo_l   = sbo   + (size_t)l*CC;
        const float* cWqkv_l = cWqkv + (size_t)l*3*CC*CC;
        const float* cbqkv_l = cbqkv + (size_t)l*3*CC;
        const float* cWo_l   = cWo   + (size_t)l*CC*CC;
        const float* cbo_l   = cbo   + (size_t)l*CC;
        const float* fc1w_l  = fc1w  + (size_t)l*FF*CC;
        const float* fc1b_l  = fc1b  + (size_t)l*FF;
        const float* fc2w_l  = fc2w  + (size_t)l*CC*FF;
        const float* fc2b_l  = fc2b  + (size_t)l*CC;

        // ---- self-attention ----
        gemm_bf16s<false><<<dim3(3*CC/BM, MR/BM), 256>>>(px, sWqkv_l, sbqkv_l, pqkv, 3*CC, CC);
        split_heads_qk<<<BHH*TT*HDD/256, 256>>>(pqkv, 3*CC, pqkv + CC, 3*CC);
        transpose_v<<<dim3(TT/32, HDD/32, BHH), 256>>>(pqkv + 2*CC, 3*CC);
        run_attention(pqh, pkh, 1);
        merge_heads<<<MR*CC/256, 256>>>(pq);
        gemm_bf16s<false><<<dim3(CC/BM, MR/BM), 256>>>(pq, sWo_l, sbo_l, ptmp, CC, CC);
        add_ln<<<MR, 128>>>(px, ptmp, ln1g + l*CC, ln1b + l*CC);

        // ---- cross-attention ----
        gemm_bf16s<false><<<dim3(CC/BM, MR/BM), 256>>>(px, cWqkv_l, cbqkv_l, pq, CC, CC);
        gemm_bf16s<false><<<dim3(2*CC/BM, MR/BM), 256>>>(enc, cWqkv_l + (size_t)CC*CC,
                                                         cbqkv_l + CC, pkv, 2*CC, CC);
        split_heads_qk<<<BHH*TT*HDD/256, 256>>>(pq, CC, pkv, 2*CC);
        transpose_v<<<dim3(TT/32, HDD/32, BHH), 256>>>(pkv + CC, 2*CC);
        run_attention(pqh, pkh, 0);
        merge_heads<<<MR*CC/256, 256>>>(pq);
        gemm_bf16s<false><<<dim3(CC/BM, MR/BM), 256>>>(pq, cWo_l, cbo_l, ptmp, CC, CC);
        add_ln<<<MR, 128>>>(px, ptmp, ln2g + l*CC, ln2b + l*CC);

        // ---- FFN ----
        gemm_bf16s<true ><<<dim3(FF/BM, MR/BM), 256>>>(px, fc1w_l, fc1b_l, ph, FF, CC);
        gemm_bf16s<false><<<dim3(CC/BM, MR/BM), 256>>>(ph, fc2w_l, fc2b_l, ptmp, CC, FF);
        add_ln<<<MR, 128>>>(px, ptmp, ln3g + l*CC, ln3b + l*CC);
    }

    copy_out<<<MR*CC/256, 256>>>((float*)d_out);
}

// round 3
// speedup vs baseline: 5.4555x; 1.0712x over previous
#include <cuda_runtime.h>
#include <cuda_bf16.h>
#include <math.h>
#include <stdint.h>
#include <stddef.h>

// Problem dims (fixed)
#define TT 2048
#define BB 2
#define CC 512
#define HH 8
#define HDD 64
#define FF 2048
#define NLAYER 4
#define MR (TT*BB)
#define BHH (BB*HH)

#define BM 128
#define BK 32

// fused attention tiling
#define KSTR 34
#define TILEW (64*KSTR)                 // words per (array, buffer)
#define SMEM_FUSED (8*TILEW*4)          // Kh,Kl,Vh,Vl x 2 buffers

// ---------------- scratch (device globals; no allocs allowed) ----------------
__device__ float g_x[MR*CC];
__device__ float g_tmp[MR*CC];
__device__ float g_qkv[MR*3*CC];
__device__ float g_q[MR*CC];
__device__ float g_kv[MR*2*CC];
__device__ float g_qh[BHH*TT*HDD];
__device__ float g_kh[BHH*TT*HDD];
__device__ float g_vt[BHH*HDD*TT];      // V transposed: [bh][d][t]
__device__ float g_ah[BHH*TT*HDD];      // U = raw_scores @ V
__device__ float g_h[MR*FF];
__device__ float g_colsum[BHH*HDD];     // sum_s V[s][d] per (bh,d)
__device__ unsigned g_enc[2];           // ordered-encoded min/max
__device__ float g_mm[2];               // [min, 1/(max-min)]

// ---------------- helpers ----------------
__device__ __forceinline__ unsigned fenc(float x) {
    unsigned u = __float_as_uint(x);
    return (u & 0x80000000u) ? ~u : (u | 0x80000000u);
}
__device__ __forceinline__ float fdec(unsigned e) {
    unsigned u = (e & 0x80000000u) ? (e & 0x7FFFFFFFu) : ~e;
    return __uint_as_float(u);
}

__device__ __forceinline__ void split2(float x0, float x1, unsigned &h, unsigned &l) {
    __nv_bfloat162 hb = __floats2bfloat162_rn(x0, x1);
    float r0 = x0 - __bfloat162float(hb.x);
    float r1 = x1 - __bfloat162float(hb.y);
    __nv_bfloat162 lb = __floats2bfloat162_rn(r0, r1);
    h = *reinterpret_cast<unsigned*>(&hb);
    l = *reinterpret_cast<unsigned*>(&lb);
}

__device__ __forceinline__ void mma_bf16(float (&d)[4], const unsigned (&a)[4], const unsigned (&b)[2]) {
    asm volatile("mma.sync.aligned.m16n8k16.row.col.f32.bf16.bf16.f32 "
        "{%0,%1,%2,%3},{%4,%5,%6,%7},{%8,%9},{%0,%1,%2,%3};\n"
        : "+f"(d[0]), "+f"(d[1]), "+f"(d[2]), "+f"(d[3])
        : "r"(a[0]), "r"(a[1]), "r"(a[2]), "r"(a[3]), "r"(b[0]), "r"(b[1]));
}

// ---------------- positional embedding + input add ----------------
__global__ void __launch_bounds__(256) pos_embed_kernel(
    const float* __restrict__ xin, const int* __restrict__ tokens)
{
    int idx = blockIdx.x * 256 + threadIdx.x;
    if (idx >= MR*CC) return;
    int c = idx & (CC-1);
    int r = idx >> 9;
    int b = r & 1;
    int t = r >> 1;
    float pe = 0.f;
    if (tokens[b*TT + t] != 0) {
        int j = (c < 256) ? c : c - 256;
        float freq = expf((float)j * (-9.210340371976184f / 255.0f));
        float ang = (float)(t + 1) * freq;
        pe = (c < 256) ? sinf(ang) : cosf(ang);
    }
    g_x[idx] = xin[idx] + pe;
}

// ================= split-bf16 TN GEMM: out[M,N] = A[M,K] @ W[N,K]^T + bias =================
template<bool RELU>
__global__ void __launch_bounds__(256, 1) gemm_bf16s(
    const float* __restrict__ A, const float* __restrict__ W,
    const float* __restrict__ bias, float* __restrict__ out,
    int N, int K)
{
    __shared__ unsigned Ah[BM*20], Al[BM*20], Bh[BM*20], Bl[BM*20];
    const int tid = threadIdx.x;
    const int m0 = blockIdx.y * BM, n0 = blockIdx.x * BM;
    const int prow = tid >> 3, pk = (tid & 7) << 2;
    const float* Ap = A + (size_t)(m0 + prow) * K + pk;
    const float* Wp = W + (size_t)(n0 + prow) * K + pk;

    float4 ra[4], rb[4];
    #pragma unroll
    for (int r = 0; r < 4; r++) {
        ra[r] = *(const float4*)(Ap + (size_t)r*32*K);
        rb[r] = *(const float4*)(Wp + (size_t)r*32*K);
    }

    const int wid = tid >> 5, lane = tid & 31;
    const int wy = wid >> 2, wx = wid & 3;
    const int lq = lane >> 2, lr = lane & 3;
    const int wm = wy * 64, wn = wx * 32;

    float acc[4][4][4];
    #pragma unroll
    for (int i = 0; i < 4; i++)
        #pragma unroll
        for (int j = 0; j < 4; j++)
            #pragma unroll
            for (int q = 0; q < 4; q++) acc[i][j][q] = 0.f;

    const int KT = K / BK;
    for (int kt = 0; kt < KT; kt++) {
        #pragma unroll
        for (int r = 0; r < 4; r++) {
            int ad = (prow + 32*r)*20 + (pk >> 1);
            unsigned h0,l0,h1,l1;
            split2(ra[r].x, ra[r].y, h0, l0); split2(ra[r].z, ra[r].w, h1, l1);
            *(uint2*)&Ah[ad] = make_uint2(h0, h1);
            *(uint2*)&Al[ad] = make_uint2(l0, l1);
            split2(rb[r].x, rb[r].y, h0, l0); split2(rb[r].z, rb[r].w, h1, l1);
            *(uint2*)&Bh[ad] = make_uint2(h0, h1);
            *(uint2*)&Bl[ad] = make_uint2(l0, l1);
        }
        __syncthreads();
        if (kt + 1 < KT) {
            #pragma unroll
            for (int r = 0; r < 4; r++) {
                ra[r] = *(const float4*)(Ap + (kt+1)*BK + (size_t)r*32*K);
                rb[r] = *(const float4*)(Wp + (kt+1)*BK + (size_t)r*32*K);
            }
        }
        #pragma unroll
        for (int ks = 0; ks < 2; ks++) {
            const int kw = ks * 8;
            unsigned ah[4][4], al_[4][4];
            #pragma unroll
            for (int mt = 0; mt < 4; mt++) {
                int ba = (wm + mt*16 + lq)*20 + kw + lr;
                ah[mt][0]=Ah[ba];     ah[mt][1]=Ah[ba+160];
                ah[mt][2]=Ah[ba+4];   ah[mt][3]=Ah[ba+164];
                al_[mt][0]=Al[ba];    al_[mt][1]=Al[ba+160];
                al_[mt][2]=Al[ba+4];  al_[mt][3]=Al[ba+164];
            }
            unsigned bh_[4][2], bl_[4][2];
            #pragma unroll
            for (int nt = 0; nt < 4; nt++) {
                int bb = (wn + nt*8 + lq)*20 + kw + lr;
                bh_[nt][0]=Bh[bb]; bh_[nt][1]=Bh[bb+4];
                bl_[nt][0]=Bl[bb]; bl_[nt][1]=Bl[bb+4];
            }
            #pragma unroll
            for (int mt = 0; mt < 4; mt++)
                #pragma unroll
                for (int nt = 0; nt < 4; nt++) {
                    mma_bf16(acc[mt][nt], ah[mt],  bh_[nt]);
                    mma_bf16(acc[mt][nt], ah[mt],  bl_[nt]);
                    mma_bf16(acc[mt][nt], al_[mt], bh_[nt]);
                }
        }
        __syncthreads();
    }

    #pragma unroll
    for (int mt = 0; mt < 4; mt++) {
        int m = m0 + wm + mt*16 + lq;
        #pragma unroll
        for (int nt = 0; nt < 4; nt++) {
            int n = n0 + wn + nt*8 + 2*lr;
            float2 bv = *(const float2*)(bias + n);
            float v0 = acc[mt][nt][0] + bv.x;
            float v1 = acc[mt][nt][1] + bv.y;
            float v2 = acc[mt][nt][2] + bv.x;
            float v3 = acc[mt][nt][3] + bv.y;
            if (RELU) { v0=fmaxf(v0,0.f); v1=fmaxf(v1,0.f); v2=fmaxf(v2,0.f); v3=fmaxf(v3,0.f); }
            *(float2*)(out + (size_t)m*N + n)     = make_float2(v0, v1);
            *(float2*)(out + (size_t)(m+8)*N + n) = make_float2(v2, v3);
        }
    }
}

// ================= fused attention: U = (masked scores) @ V, global min/max tracked =================
// t-tile = 128 rows (8 warps x 16), s-tile = 64; K and V^T staged in smem (hi/lo), double-buffered.
__global__ void __launch_bounds__(256, 1) attn_fused(int causal)
{
    extern __shared__ unsigned sm[];
    unsigned* Kh = sm;
    unsigned* Kl = sm + 2*TILEW;
    unsigned* Vh = sm + 4*TILEW;
    unsigned* Vl = sm + 6*TILEW;
    __shared__ float rlo[8], rhi[8];

    const int bh = blockIdx.y;
    const int t0 = (gridDim.x - 1 - blockIdx.x) * 128;   // heavy tiles first (causal balance)
    const int tid = threadIdx.x;
    const int wid = tid >> 5, lane = tid & 31;
    const int lq = lane >> 2, lr = lane & 3;
    const int trow = t0 + wid*16 + lq;

    // ---- Q fragments (hi/lo) in registers ----
    unsigned qah[4][4], qal[4][4];
    {
        const float* qp = g_qh + ((size_t)bh*TT + trow) * HDD;
        #pragma unroll
        for (int ks = 0; ks < 4; ks++) {
            int kb = ks*16 + 2*lr;
            float2 a01 = *(const float2*)(qp + kb);
            float2 a23 = *(const float2*)(qp + 8*HDD + kb);
            float2 a45 = *(const float2*)(qp + kb + 8);
            float2 a67 = *(const float2*)(qp + 8*HDD + kb + 8);
            split2(a01.x, a01.y, qah[ks][0], qal[ks][0]);
            split2(a23.x, a23.y, qah[ks][1], qal[ks][1]);
            split2(a45.x, a45.y, qah[ks][2], qal[ks][2]);
            split2(a67.x, a67.y, qah[ks][3], qal[ks][3]);
        }
    }

    float uacc[8][4];
    #pragma unroll
    for (int i = 0; i < 8; i++)
        #pragma unroll
        for (int q = 0; q < 4; q++) uacc[i][q] = 0.f;

    float lo = 3.4e38f, hi = -3.4e38f;

    const int nst = causal ? (t0/64 + 2) : (TT/64);

    // cooperative loader indices: 64 rows x 4 threads/row, 4 float4 each
    const int prow = tid >> 2;
    const int pk = (tid & 3) * 16;           // float offset within 64
    const int wbase0 = prow*KSTR + (tid & 3)*8;

    float4 kf[4], vf[4];
    // prologue: load tile 0
    {
        const float* kp = g_kh + ((size_t)bh*TT + 0 + prow) * HDD + pk;
        const float* vp = g_vt + ((size_t)bh*HDD + prow) * TT + 0 + pk;
        #pragma unroll
        for (int i = 0; i < 4; i++) { kf[i] = *(const float4*)(kp + 4*i); vf[i] = *(const float4*)(vp + 4*i); }
    }
    // store tile 0 to buffer 0
    {
        int wb = wbase0;
        #pragma unroll
        for (int i = 0; i < 4; i++) {
            unsigned h0,l0,h1,l1;
            split2(kf[i].x, kf[i].y, h0, l0); split2(kf[i].z, kf[i].w, h1, l1);
            *(uint2*)&Kh[wb + 2*i] = make_uint2(h0, h1);
            *(uint2*)&Kl[wb + 2*i] = make_uint2(l0, l1);
            split2(vf[i].x, vf[i].y, h0, l0); split2(vf[i].z, vf[i].w, h1, l1);
            *(uint2*)&Vh[wb + 2*i] = make_uint2(h0, h1);
            *(uint2*)&Vl[wb + 2*i] = make_uint2(l0, l1);
        }
    }
    __syncthreads();

    for (int st = 0; st < nst; st++) {
        const int buf = (st & 1) * TILEW;
        const int s0 = st * 64;

        // prefetch next tile into registers
        if (st + 1 < nst) {
            int sn = (st+1) * 64;
            const float* kp = g_kh + ((size_t)bh*TT + sn + prow) * HDD + pk;
            const float* vp = g_vt + ((size_t)bh*HDD + prow) * TT + sn + pk;
            #pragma unroll
            for (int i = 0; i < 4; i++) { kf[i] = *(const float4*)(kp + 4*i); vf[i] = *(const float4*)(vp + 4*i); }
        }

        // ---- S = Q K^T for this s-tile ----
        float sacc[8][4];
        #pragma unroll
        for (int i = 0; i < 8; i++)
            #pragma unroll
            for (int q = 0; q < 4; q++) sacc[i][q] = 0.f;

        #pragma unroll
        for (int ks = 0; ks < 4; ks++) {
            #pragma unroll
            for (int nt = 0; nt < 8; nt++) {
                int ba = buf + (nt*8 + lq)*KSTR + ks*8 + lr;
                unsigned bb[2]  = { Kh[ba], Kh[ba+4] };
                unsigned bl2[2] = { Kl[ba], Kl[ba+4] };
                mma_bf16(sacc[nt], qah[ks], bb);
                mma_bf16(sacc[nt], qal[ks], bb);
                mma_bf16(sacc[nt], qah[ks], bl2);
            }
        }

        // ---- mask (causal) + min/max ----
        if (causal) {
            #pragma unroll
            for (int nt = 0; nt < 8; nt++) {
                int sg = s0 + nt*8 + 2*lr;
                if (sg     > trow)     sacc[nt][0] = 0.f;
                if (sg + 1 > trow)     sacc[nt][1] = 0.f;
                if (sg     > trow + 8) sacc[nt][2] = 0.f;
                if (sg + 1 > trow + 8) sacc[nt][3] = 0.f;
            }
        }
        #pragma unroll
        for (int nt = 0; nt < 8; nt++) {
            lo = fminf(lo, fminf(fminf(sacc[nt][0], sacc[nt][1]), fminf(sacc[nt][2], sacc[nt][3])));
            hi = fmaxf(hi, fmaxf(fmaxf(sacc[nt][0], sacc[nt][1]), fmaxf(sacc[nt][2], sacc[nt][3])));
        }

        // ---- U += S @ V (S re-fragmented from accumulators, split hi/lo) ----
        #pragma unroll
        for (int ks = 0; ks < 4; ks++) {
            unsigned sah[4], sal[4];
            split2(sacc[2*ks  ][0], sacc[2*ks  ][1], sah[0], sal[0]);
            split2(sacc[2*ks  ][2], sacc[2*ks  ][3], sah[1], sal[1]);
            split2(sacc[2*ks+1][0], sacc[2*ks+1][1], sah[2], sal[2]);
            split2(sacc[2*ks+1][2], sacc[2*ks+1][3], sah[3], sal[3]);
            #pragma unroll
            for (int dt = 0; dt < 8; dt++) {
                int ba = buf + (dt*8 + lq)*KSTR + ks*8 + lr;
                unsigned vb[2]  = { Vh[ba], Vh[ba+4] };
                unsigned vl2[2] = { Vl[ba], Vl[ba+4] };
                mma_bf16(uacc[dt], sah, vb);
                mma_bf16(uacc[dt], sal, vb);
                mma_bf16(uacc[dt], sah, vl2);
            }
        }

        __syncthreads();   // done reading buf
        if (st + 1 < nst) {
            int wb = ((st+1) & 1) * TILEW + wbase0;
            #pragma unroll
            for (int i = 0; i < 4; i++) {
                unsigned h0,l0,h1,l1;
                split2(kf[i].x, kf[i].y, h0, l0); split2(kf[i].z, kf[i].w, h1, l1);
                *(uint2*)&Kh[wb + 2*i] = make_uint2(h0, h1);
                *(uint2*)&Kl[wb + 2*i] = make_uint2(l0, l1);
                split2(vf[i].x, vf[i].y, h0, l0); split2(vf[i].z, vf[i].w, h1, l1);
                *(uint2*)&Vh[wb + 2*i] = make_uint2(h0, h1);
                *(uint2*)&Vl[wb + 2*i] = make_uint2(l0, l1);
            }
            __syncthreads();
        }
    }

    // ---- store U ----
    #pragma unroll
    for (int dt = 0; dt < 8; dt++) {
        int n = dt*8 + 2*lr;
        *(float2*)(g_ah + ((size_t)bh*TT + trow)*HDD + n)     = make_float2(uacc[dt][0], uacc[dt][1]);
        *(float2*)(g_ah + ((size_t)bh*TT + trow + 8)*HDD + n) = make_float2(uacc[dt][2], uacc[dt][3]);
    }

    // ---- block min/max -> global atomics ----
    #pragma unroll
    for (int o = 16; o > 0; o >>= 1) {
        lo = fminf(lo, __shfl_xor_sync(0xFFFFFFFFu, lo, o));
        hi = fmaxf(hi, __shfl_xor_sync(0xFFFFFFFFu, hi, o));
    }
    if (lane == 0) { rlo[wid] = lo; rhi[wid] = hi; }
    __syncthreads();
    if (tid == 0) {
        float l2 = rlo[0], h2 = rhi[0];
        #pragma unroll
        for (int w = 1; w < 8; w++) { l2 = fminf(l2, rlo[w]); h2 = fmaxf(h2, rhi[w]); }
        atomicMin(&g_enc[0], fenc(l2));
        atomicMax(&g_enc[1], fenc(h2));
    }
}

// ---------------- min/max bookkeeping ----------------
__global__ void mm_reset(int causal) {
    unsigned z = fenc(0.f);
    g_enc[0] = causal ? z : 0xFFFFFFFFu;
    g_enc[1] = causal ? z : 0u;
}
__global__ void mm_final() {
    float mn = fdec(g_enc[0]), mx = fdec(g_enc[1]);
    g_mm[0] = mn; g_mm[1] = 1.0f / (mx - mn);
}

// ---------------- split heads (q,k): [T*B, ...] -> [B*H, T, hd], q scaled ----------------
__global__ void __launch_bounds__(256) split_heads_qk(
    const float* __restrict__ qsrc, int qld,
    const float* __restrict__ ksrc, int kld)
{
    int idx = blockIdx.x * 256 + threadIdx.x;
    if (idx >= BHH*TT*HDD) return;
    int d  = idx & 63;
    int t  = (idx >> 6) & (TT-1);
    int bh = idx >> 17;
    int b = bh >> 3, h = bh & 7;
    size_t r = (size_t)t * BB + b;
    int c = h * HDD + d;
    g_qh[idx] = qsrc[r * qld + c] * 0.125f;
    g_kh[idx] = ksrc[r * kld + c];
}

// ---------------- transpose V into [bh][d][t] ----------------
__global__ void __launch_bounds__(256) transpose_v(
    const float* __restrict__ vsrc, int ldv)
{
    __shared__ float tile[32][33];
    const int bh = blockIdx.z;
    const int b = bh >> 3, h = bh & 7;
    const int t0 = blockIdx.x * 32, d0 = blockIdx.y * 32;
    const int tx = threadIdx.x & 31, ty = threadIdx.x >> 5;
    #pragma unroll
    for (int j = ty; j < 32; j += 8)
        tile[j][tx] = vsrc[(size_t)((t0 + j)*BB + b) * ldv + h*HDD + d0 + tx];
    __syncthreads();
    #pragma unroll
    for (int j = ty; j < 32; j += 8)
        g_vt[((size_t)bh*HDD + d0 + j) * TT + t0 + tx] = tile[tx][j];
}

// ---------------- column sums of V per (bh, d) ----------------
__global__ void __launch_bounds__(256) colsum_v()
{
    const int bh = blockIdx.x;
    const int wid = threadIdx.x >> 5, lane = threadIdx.x & 31;
    #pragma unroll
    for (int j = 0; j < 8; j++) {
        int d = wid*8 + j;
        const float4* p = (const float4*)(g_vt + ((size_t)bh*HDD + d) * TT);
        float s = 0.f;
        for (int i = lane; i < TT/4; i += 32) {
            float4 v = p[i];
            s += v.x + v.y + v.z + v.w;
        }
        #pragma unroll
        for (int o = 16; o > 0; o >>= 1) s += __shfl_xor_sync(0xFFFFFFFFu, s, o);
        if (lane == 0) g_colsum[bh*HDD + d] = s;
    }
}

// ---------------- merge heads + normalization epilogue ----------------
// a = inv*U - mn*inv*colsumV, reshaped [B*H,T,hd] -> [T*B,C]
__global__ void __launch_bounds__(256) merge_heads(float* __restrict__ a)
{
    int idx = blockIdx.x * 256 + threadIdx.x;
    if (idx >= MR*CC) return;
    int c = idx & (CC-1);
    int r = idx >> 9;
    int b = r & 1;
    int t = r >> 1;
    int h = c >> 6, d = c & 63;
    int bh = b*HH + h;
    float inv = g_mm[1];
    float k2 = g_mm[0] * inv;    // mn*inv
    float u = g_ah[((size_t)bh*TT + t)*HDD + d];
    a[idx] = inv*u - k2*g_colsum[bh*HDD + d];
}

// ---------------- residual add + LayerNorm (in-place on x) ----------------
__global__ void __launch_bounds__(128) add_ln(
    float* __restrict__ x, const float* __restrict__ dlt,
    const float* __restrict__ g, const float* __restrict__ b)
{
    const int r = blockIdx.x;
    const int tid = threadIdx.x;
    __shared__ float sred[128];
    float4 xv = *(float4*)(x + (size_t)r*CC + tid*4);
    float4 dv = *(const float4*)(dlt + (size_t)r*CC + tid*4);
    float y0 = xv.x+dv.x, y1 = xv.y+dv.y, y2 = xv.z+dv.z, y3 = xv.w+dv.w;

    sred[tid] = y0+y1+y2+y3;
    __syncthreads();
    for (int s = 64; s > 0; s >>= 1) {
        if (tid < s) sred[tid] += sred[tid+s];
        __syncthreads();
    }
    float mu = sred[0] * (1.0f/CC);
    __syncthreads();

    float d0 = y0-mu, d1 = y1-mu, d2 = y2-mu, d3 = y3-mu;
    sred[tid] = d0*d0 + d1*d1 + d2*d2 + d3*d3;
    __syncthreads();
    for (int s = 64; s > 0; s >>= 1) {
        if (tid < s) sred[tid] += sred[tid+s];
        __syncthreads();
    }
    float rstd = rsqrtf(sred[0] * (1.0f/CC) + 1e-20f);

    float4 gv = *(const float4*)(g + tid*4);
    float4 bv = *(const float4*)(b + tid*4);
    float4 ov;
    ov.x = d0*rstd*gv.x + bv.x;
    ov.y = d1*rstd*gv.y + bv.y;
    ov.z = d2*rstd*gv.z + bv.z;
    ov.w = d3*rstd*gv.w + bv.w;
    *(float4*)(x + (size_t)r*CC + tid*4) = ov;
}

__global__ void __launch_bounds__(256) copy_out(float* __restrict__ out)
{
    int idx = blockIdx.x * 256 + threadIdx.x;
    if (idx < MR*CC) out[idx] = g_x[idx];
}

// ---------------- host orchestration ----------------
static void run_attention(int causal)
{
    mm_reset<<<1, 1>>>(causal);
    attn_fused<<<dim3(TT/128, BHH), 256, SMEM_FUSED>>>(causal);
    mm_final<<<1, 1>>>();
}

extern "C" void kernel_launch(void* const* d_in, const int* in_sizes, int n_in,
                              void* d_out, int out_size)
{
    const float* x       = (const float*)d_in[0];
    const float* enc     = (const float*)d_in[1];
    const int*   tokens  = (const int*)  d_in[2];
    const float* sWqkv   = (const float*)d_in[3];
    const float* sbqkv   = (const float*)d_in[4];
    const float* sWo     = (const float*)d_in[5];
    const float* sbo     = (const float*)d_in[6];
    const float* cWqkv   = (const float*)d_in[7];
    const float* cbqkv   = (const float*)d_in[8];
    const float* cWo     = (const float*)d_in[9];
    const float* cbo     = (const float*)d_in[10];
    const float* fc1w    = (const float*)d_in[11];
    const float* fc1b    = (const float*)d_in[12];
    const float* fc2w    = (const float*)d_in[13];
    const float* fc2b    = (const float*)d_in[14];
    const float* ln1g    = (const float*)d_in[15];
    const float* ln1b    = (const float*)d_in[16];
    const float* ln2g    = (const float*)d_in[17];
    const float* ln2b    = (const float*)d_in[18];
    const float* ln3g    = (const float*)d_in[19];
    const float* ln3b    = (const float*)d_in[20];

    static int smem_set = 0;
    if (!smem_set) {
        cudaFuncSetAttribute(attn_fused, cudaFuncAttributeMaxDynamicSharedMemorySize, SMEM_FUSED);
        smem_set = 1;
    }

    float *px, *ptmp, *pqkv, *pq, *pkv;
    cudaGetSymbolAddress((void**)&px,   g_x);
    cudaGetSymbolAddress((void**)&ptmp, g_tmp);
    cudaGetSymbolAddress((void**)&pqkv, g_qkv);
    cudaGetSymbolAddress((void**)&pq,   g_q);
    cudaGetSymbolAddress((void**)&pkv,  g_kv);
    float* ph;
    cudaGetSymbolAddress((void**)&ph,   g_h);

    pos_embed_kernel<<<MR*CC/256, 256>>>(x, tokens);

    for (int l = 0; l < NLAYER; l++) {
        const float* sWqkv_l = sWqkv + (size_t)l*3*CC*CC;
        const float* sbqkv_l = sbqkv + (size_t)l*3*CC;
        const float* sWo_l   = sWo   + (size_t)l*CC*CC;
        const float* sbo_l   = sbo   + (size_t)l*CC;
        const float* cWqkv_l = cWqkv + (size_t)l*3*CC*CC;
        const float* cbqkv_l = cbqkv + (size_t)l*3*CC;
        const float* cWo_l   = cWo   + (size_t)l*CC*CC;
        const float* cbo_l   = cbo   + (size_t)l*CC;
        const float* fc1w_l  = fc1w  + (size_t)l*FF*CC;
        const float* fc1b_l  = fc1b  + (size_t)l*FF;
        const float* fc2w_l  = fc2w  + (size_t)l*CC*FF;
        const float* fc2b_l  = fc2b  + (size_t)l*CC;

        // ---- self-attention ----
        gemm_bf16s<false><<<dim3(3*CC/BM, MR/BM), 256>>>(px, sWqkv_l, sbqkv_l, pqkv, 3*CC, CC);
        split_heads_qk<<<BHH*TT*HDD/256, 256>>>(pqkv, 3*CC, pqkv + CC, 3*CC);
        transpose_v<<<dim3(TT/32, HDD/32, BHH), 256>>>(pqkv + 2*CC, 3*CC);
        colsum_v<<<BHH, 256>>>();
        run_attention(1);
        merge_heads<<<MR*CC/256, 256>>>(pq);
        gemm_bf16s<false><<<dim3(CC/BM, MR/BM), 256>>>(pq, sWo_l, sbo_l, ptmp, CC, CC);
        add_ln<<<MR, 128>>>(px, ptmp, ln1g + l*CC, ln1b + l*CC);

        // ---- cross-attention ----
        gemm_bf16s<false><<<dim3(CC/BM, MR/BM), 256>>>(px, cWqkv_l, cbqkv_l, pq, CC, CC);
        gemm_bf16s<false><<<dim3(2*CC/BM, MR/BM), 256>>>(enc, cWqkv_l + (size_t)CC*CC,
                                                         cbqkv_l + CC, pkv, 2*CC, CC);
        split_heads_qk<<<BHH*TT*HDD/256, 256>>>(pq, CC, pkv, 2*CC);
        transpose_v<<<dim3(TT/32, HDD/32, BHH), 256>>>(pkv + CC, 2*CC);
        colsum_v<<<BHH, 256>>>();
        run_attention(0);
        merge_heads<<<MR*CC/256, 256>>>(pq);
        gemm_bf16s<false><<<dim3(CC/BM, MR/BM), 256>>>(pq, cWo_l, cbo_l, ptmp, CC, CC);
        add_ln<<<MR, 128>>>(px, ptmp, ln2g + l*CC, ln2b + l*CC);

        // ---- FFN ----
        gemm_bf16s<true ><<<dim3(FF/BM, MR/BM), 256>>>(px, fc1w_l, fc1b_l, ph, FF, CC);
        gemm_bf16s<false><<<dim3(CC/BM, MR/BM), 256>>>(ph, fc2w_l, fc2b_l, ptmp, CC, FF);
        add_ln<<<MR, 128>>>(px, ptmp, ln3g + l*CC, ln3b + l*CC);
    }

    copy_out<<<MR*CC/256, 256>>>((float*)d_out);
}